// round 3
// baseline (speedup 1.0000x reference)
#include <cuda_runtime.h>
#include <cuda_bf16.h>

// Problem constants
#define BATCH      32
#define DIM        64
#define HW         4096          // 64*64
#define NPIX       131072        // 32*4096
#define KCODES     512
#define PIXPB      128           // pixels per block
#define NBLOCKS    1024          // NPIX / PIXPB
#define THREADS    256
#define KCHUNK     128
#define NCHUNK     4             // KCODES / KCHUNK
#define XS         264           // Xd row stride in floats (128 dup pairs + pad)
#define RSTR       132           // Ws row stride (128 + 4 pad, 16B aligned)
#define QOFF       131072        // quantized offset in d_out (floats)
#define LOFF       8519680       // loss offset = 131072 + 8388608
#define NELEM_Q    8388608.0

__device__ float g_part[NBLOCKS];   // per-block loss partials (written every replay)

typedef unsigned long long ull;

// ---- packed fp32 helpers (each lane is an exact fp32 rn op) ------------
__device__ __forceinline__ ull ffma2(ull a, ull b, ull c) {
    ull d;
    asm("fma.rn.f32x2 %0, %1, %2, %3;" : "=l"(d) : "l"(a), "l"(b), "l"(c));
    return d;
}
__device__ __forceinline__ ull fadd2(ull a, ull b) {
    ull d;
    asm("add.rn.f32x2 %0, %1, %2;" : "=l"(d) : "l"(a), "l"(b));
    return d;
}
__device__ __forceinline__ ull dup2(float x) {
    ull d;
    asm("mov.b64 %0, {%1, %1};" : "=l"(d) : "f"(x));
    return d;
}
__device__ __forceinline__ float2 unpack2(ull v) {
    float lo, hi;
    asm("mov.b64 {%0, %1}, %2;" : "=f"(lo), "=f"(hi) : "l"(v));
    return make_float2(lo, hi);
}

// ---------------------------------------------------------------------------
// main: fused distance-GEMM (packed FFMA2, zero-pack inner loop) + argmin +
//       gather + straight-through output + loss partial
// ---------------------------------------------------------------------------
__global__ __launch_bounds__(THREADS, 2)
void vq_main(const float* __restrict__ in, const float* __restrict__ wt,
             float* __restrict__ out) {
    extern __shared__ float sm[];
    float* Xd = sm;                   // [64][XS]: Xd[d][2j],Xd[d][2j+1] = x_j dup
    float* Ws = sm + DIM * XS;        // [64][RSTR]: Ws[d][k] = w of code k, dim d

    __shared__ float cs[PIXPB];       // ||x||^2 per pixel
    __shared__ int   idxs[PIXPB];     // final argmin per pixel
    __shared__ float wsqs[KCODES];    // ||w_k||^2
    __shared__ float warp_part[8];

    const int tid   = threadIdx.x;
    const int pbase = blockIdx.x * PIXPB;
    const int b     = pbase >> 12;            // pbase / 4096
    const int hw    = pbase & 4095;
    const float* inb = in + (size_t)b * (DIM * HW) + hw;

    // Load X tile duplicated: Xd[d][2j..2j+1] = x, coalesced gmem reads
    for (int i = tid; i < DIM * PIXPB; i += THREADS) {
        int d = i >> 7, j = i & 127;
        float v = inb[d * HW + j];
        *(reinterpret_cast<float2*>(Xd + d * XS) + j) = make_float2(v, v);
    }

    // ||w_k||^2 per block (L2-resident; overlaps the X-tile LDG latency).
    // Reference rounding: product rounded, sequential adds in d order.
    #pragma unroll
    for (int r = 0; r < 2; ++r) {
        int k = tid + r * THREADS;
        const float4* w4 = reinterpret_cast<const float4*>(wt + k * DIM);
        float c = 0.0f;
        #pragma unroll
        for (int q = 0; q < 16; ++q) {
            float4 v = w4[q];
            c = __fadd_rn(c, __fmul_rn(v.x, v.x));
            c = __fadd_rn(c, __fmul_rn(v.y, v.y));
            c = __fadd_rn(c, __fmul_rn(v.z, v.z));
            c = __fadd_rn(c, __fmul_rn(v.w, v.w));
        }
        wsqs[k] = c;
    }
    __syncthreads();

    // ||x||^2 per pixel: product-rounded, sequential sum (mimic sum(flat*flat))
    if (tid < PIXPB) {
        float c = 0.0f;
        #pragma unroll 8
        for (int d = 0; d < DIM; ++d) {
            float x = Xd[d * XS + 2 * tid];
            c = __fadd_rn(c, __fmul_rn(x, x));
        }
        cs[tid] = c;
    }

    const int ty = tid >> 4;   // 0..15 : pixel group (8 pixels)
    const int tx = tid & 15;   // 0..15 : code group (8 codes within chunk)
    const ull NEG2 = dup2(-2.0f);

    float bs[8];
    int   bi[8];
    #pragma unroll
    for (int i = 0; i < 8; ++i) { bs[i] = __int_as_float(0x7f800000); bi[i] = 0; }

    for (int ch = 0; ch < NCHUNK; ++ch) {
        __syncthreads();   // protect Ws reuse
        // Load W chunk transposed: Ws[d][k_local] = wt[(ch*128+k)*64 + d]
        for (int i = tid; i < KCHUNK * DIM; i += THREADS) {
            int k = i >> 6, d = i & 63;
            Ws[d * RSTR + k] = wt[(ch * KCHUNK + k) * DIM + d];
        }
        __syncthreads();

        // accp[pixel][codepair] : lanes = (code 2jj, code 2jj+1), exact fp32
        ull accp[8][4];
        #pragma unroll
        for (int i = 0; i < 8; ++i)
            #pragma unroll
            for (int jj = 0; jj < 4; ++jj) accp[i][jj] = 0ull;

        #pragma unroll 2
        for (int d = 0; d < DIM; ++d) {
            // X dup-pairs straight from smem: xp[i] = (x_i, x_i)
            const ulonglong2 xa = *reinterpret_cast<const ulonglong2*>(Xd + d * XS + ty * 16);
            const ulonglong2 xb = *reinterpret_cast<const ulonglong2*>(Xd + d * XS + ty * 16 + 4);
            const ulonglong2 xc = *reinterpret_cast<const ulonglong2*>(Xd + d * XS + ty * 16 + 8);
            const ulonglong2 xe = *reinterpret_cast<const ulonglong2*>(Xd + d * XS + ty * 16 + 12);
            // W natural pairs from float4-aligned smem
            const ulonglong2 wa = *reinterpret_cast<const ulonglong2*>(Ws + d * RSTR + tx * 8);
            const ulonglong2 wb = *reinterpret_cast<const ulonglong2*>(Ws + d * RSTR + tx * 8 + 4);
            const ull xp[8] = {xa.x, xa.y, xb.x, xb.y, xc.x, xc.y, xe.x, xe.y};
            const ull wp[4] = {wa.x, wa.y, wb.x, wb.y};
            #pragma unroll
            for (int i = 0; i < 8; ++i) {
                #pragma unroll
                for (int jj = 0; jj < 4; ++jj)
                    accp[i][jj] = ffma2(xp[i], wp[jj], accp[i][jj]);
            }
        }

        // Packed score assembly + scalar argmin.
        // s = rn(rn(c - 2*dot) + wsq); fma(dot,-2,c)==rn(c-2*dot) exactly.
        const ulonglong2 wq0 = *reinterpret_cast<const ulonglong2*>(wsqs + ch * KCHUNK + tx * 8);
        const ulonglong2 wq1 = *reinterpret_cast<const ulonglong2*>(wsqs + ch * KCHUNK + tx * 8 + 4);
        const ull wqp[4] = {wq0.x, wq0.y, wq1.x, wq1.y};
        #pragma unroll
        for (int i = 0; i < 8; ++i) {
            const ull cdup = dup2(cs[ty * 8 + i]);
            #pragma unroll
            for (int jj = 0; jj < 4; ++jj) {
                float2 s = unpack2(fadd2(ffma2(accp[i][jj], NEG2, cdup), wqp[jj]));
                int k0 = ch * KCHUNK + tx * 8 + jj * 2;
                if (s.x < bs[i]) { bs[i] = s.x; bi[i] = k0; }
                if (s.y < bs[i]) { bs[i] = s.y; bi[i] = k0 + 1; }
            }
        }
    }

    // Cross-thread argmin reduction (reuse Ws region): 128 pixels x 16 lanes
    __syncthreads();
    float2* red = reinterpret_cast<float2*>(Ws);
    #pragma unroll
    for (int i = 0; i < 8; ++i)
        red[(ty * 8 + i) * 16 + tx] = make_float2(bs[i], __int_as_float(bi[i]));
    __syncthreads();

    if (tid < PIXPB) {
        float best = __int_as_float(0x7f800000);
        int   bk   = 0x7fffffff;
        #pragma unroll
        for (int t = 0; t < 16; ++t) {
            float2 e = red[tid * 16 + t];
            float s = e.x; int k = __float_as_int(e.y);
            if (s < best || (s == best && k < bk)) { best = s; bk = k; }
        }
        idxs[tid] = bk;
        out[pbase + tid] = (float)bk;    // discrete_latent (as fp32)
    }
    __syncthreads();

    // Epilogue: quantized (straight-through rounding!) + loss partial
    float* outq = out + QOFF + (size_t)b * (DIM * HW) + hw;
    float lsum = 0.0f;
    for (int i = tid; i < DIM * PIXPB; i += THREADS) {
        int d = i >> 7, j = i & 127;
        int k = idxs[j];
        float q = wt[k * DIM + d];
        float x = Xd[d * XS + 2 * j];
        float df = __fsub_rn(q, x);
        lsum = __fmaf_rn(df, df, lsum);
        outq[d * HW + j] = __fadd_rn(x, df);   // x + (q - x), fp32-rounded like ref
    }
    #pragma unroll
    for (int off = 16; off > 0; off >>= 1)
        lsum += __shfl_down_sync(0xffffffffu, lsum, off);
    if ((tid & 31) == 0) warp_part[tid >> 5] = lsum;
    __syncthreads();
    if (tid == 0) {
        float tot = 0.0f;
        #pragma unroll
        for (int w = 0; w < 8; ++w) tot += warp_part[w];
        g_part[blockIdx.x] = tot;
    }
}

// ---------------------------------------------------------------------------
// finalize: loss = m + 0.25*m,  m = mean((q - x)^2) over all elements
// ---------------------------------------------------------------------------
__global__ void vq_fin(float* __restrict__ out) {
    __shared__ double red[THREADS];
    const int tid = threadIdx.x;
    double t = 0.0;
    #pragma unroll
    for (int r = 0; r < NBLOCKS / THREADS; ++r)
        t += (double)g_part[tid + r * THREADS];
    red[tid] = t;
    __syncthreads();
    for (int off = THREADS / 2; off > 0; off >>= 1) {
        if (tid < off) red[tid] += red[tid + off];
        __syncthreads();
    }
    if (tid == 0) {
        double m = red[0] / NELEM_Q;
        out[LOFF] = (float)(m + 0.25 * m);
    }
}

extern "C" void kernel_launch(void* const* d_in, const int* in_sizes, int n_in,
                              void* d_out, int out_size) {
    (void)in_sizes; (void)n_in; (void)out_size;
    const float* in = (const float*)d_in[0];
    const float* wt = (const float*)d_in[1];
    float* out = (float*)d_out;

    const int smem = (DIM * XS + DIM * RSTR) * sizeof(float);   // 101376 B
    cudaFuncSetAttribute(vq_main, cudaFuncAttributeMaxDynamicSharedMemorySize, smem);

    vq_main<<<NBLOCKS, THREADS, smem>>>(in, wt, out);
    vq_fin<<<1, THREADS>>>(out);
}

// round 6
// speedup vs baseline: 1.3341x; 1.3341x over previous
#include <cuda_runtime.h>
#include <cuda_bf16.h>

// Problem constants
#define BATCH      32
#define DIM        64
#define HW         4096          // 64*64
#define NPIX       131072        // 32*4096
#define KCODES     512
#define PIXPB      128           // pixels per block
#define NBLOCKS    1024          // NPIX / PIXPB
#define THREADS    128
#define KCHUNK     128
#define NCHUNK     4             // KCODES / KCHUNK
#define RSTR       132           // smem row stride floats (528B: 16B & 8B aligned)
#define QOFF       131072        // quantized offset in d_out (floats)
#define LOFF       8519680       // loss offset = 131072 + 8388608
#define NELEM_Q    8388608.0

__device__ float g_part[NBLOCKS];   // per-block loss partials

typedef unsigned long long ull;

// ---- packed fp32 helpers (each lane is an exact fp32 rn op) ------------
__device__ __forceinline__ ull ffma2(ull a, ull b, ull c) {
    ull d;
    asm("fma.rn.f32x2 %0, %1, %2, %3;" : "=l"(d) : "l"(a), "l"(b), "l"(c));
    return d;
}
__device__ __forceinline__ ull fadd2(ull a, ull b) {
    ull d;
    asm("add.rn.f32x2 %0, %1, %2;" : "=l"(d) : "l"(a), "l"(b));
    return d;
}
__device__ __forceinline__ ull dup2(float x) {
    ull d;
    asm("mov.b64 %0, {%1, %1};" : "=l"(d) : "f"(x));
    return d;
}
__device__ __forceinline__ float2 unpack2(ull v) {
    float lo, hi;
    asm("mov.b64 {%0, %1}, %2;" : "=f"(lo), "=f"(hi) : "l"(v));
    return make_float2(lo, hi);
}

// ---------------------------------------------------------------------------
// main: fused distance-GEMM (FFMA2, conflict-free LDS) + argmin + gather +
//       straight-through output + loss partial
// Thread map: ty = tid>>3 (16 groups x 8 pixels), tx = tid&7.
// Thread tx handles code-pairs {tx, tx+8, ..., tx+56} of the 128-code chunk.
// ---------------------------------------------------------------------------
__global__ __launch_bounds__(THREADS, 2)
void vq_main(const float* __restrict__ in, const float* __restrict__ wt,
             float* __restrict__ out) {
    extern __shared__ float sm[];
    float* Xs = sm;                   // [64][RSTR]: Xs[d][j] = x of pixel j, dim d
    float* Ws = sm + DIM * RSTR;      // [64][RSTR]: Ws[d][k] = w of chunk code k, dim d

    __shared__ float cs[PIXPB];             // ||x||^2 per pixel
    __shared__ int   idxs[PIXPB];           // final argmin per pixel
    __shared__ __align__(16) float wsqs[KCODES];
    __shared__ float warp_part[4];

    const int tid   = threadIdx.x;
    const int pbase = blockIdx.x * PIXPB;
    const int b     = pbase >> 12;            // pbase / 4096
    const int hw    = pbase & 4095;
    const float* inb = in + (size_t)b * (DIM * HW) + hw;

    // Load X tile: coalesced gmem (128 consecutive floats per iter)
    #pragma unroll
    for (int d = 0; d < DIM; ++d)
        Xs[d * RSTR + tid] = inb[d * HW + tid];

    // ||w_k||^2 in-block (L2-resident; overlaps X LDG latency).
    // Reference rounding: product rounded, sequential adds in d order.
    #pragma unroll
    for (int r = 0; r < 4; ++r) {
        int k = tid + r * THREADS;
        const float4* w4 = reinterpret_cast<const float4*>(wt + k * DIM);
        float c = 0.0f;
        #pragma unroll
        for (int q = 0; q < 16; ++q) {
            float4 v = w4[q];
            c = __fadd_rn(c, __fmul_rn(v.x, v.x));
            c = __fadd_rn(c, __fmul_rn(v.y, v.y));
            c = __fadd_rn(c, __fmul_rn(v.z, v.z));
            c = __fadd_rn(c, __fmul_rn(v.w, v.w));
        }
        wsqs[k] = c;
    }
    __syncthreads();

    // ||x||^2 per pixel: product-rounded, sequential sum
    {
        float c = 0.0f;
        #pragma unroll 8
        for (int d = 0; d < DIM; ++d) {
            float x = Xs[d * RSTR + tid];
            c = __fadd_rn(c, __fmul_rn(x, x));
        }
        cs[tid] = c;
    }

    const int ty = tid >> 3;   // 0..15 : pixel group (8 pixels)
    const int tx = tid & 7;    // 0..7  : code-pair lane
    const ull NEG2 = dup2(-2.0f);

    float bs[8];
    int   bi[8];
    #pragma unroll
    for (int i = 0; i < 8; ++i) { bs[i] = __int_as_float(0x7f800000); bi[i] = 0; }

    for (int ch = 0; ch < NCHUNK; ++ch) {
        __syncthreads();   // protect Ws reuse
        // Load W chunk transposed: Ws[d][k] = wt[(ch*128+k)*64 + d]
        for (int i = tid; i < KCHUNK * DIM; i += THREADS) {
            int k = i >> 6, d = i & 63;
            Ws[d * RSTR + k] = wt[(ch * KCHUNK + k) * DIM + d];
        }
        __syncthreads();

        // accp[pixel][jj]: lanes = codes (2p, 2p+1), p = tx + 8*jj. Exact fp32.
        ull accp[8][8];
        #pragma unroll
        for (int i = 0; i < 8; ++i)
            #pragma unroll
            for (int jj = 0; jj < 8; ++jj) accp[i][jj] = 0ull;

        #pragma unroll 2
        for (int d = 0; d < DIM; ++d) {
            // X: two broadcast LDS.128 (8 pixels)
            const float4 xa = *reinterpret_cast<const float4*>(Xs + d * RSTR + ty * 8);
            const float4 xb = *reinterpret_cast<const float4*>(Xs + d * RSTR + ty * 8 + 4);
            // W: 8 conflict-free LDS.64 — lanes (8 tx) read one contiguous 64B block
            const ull* wrow = reinterpret_cast<const ull*>(Ws + d * RSTR);
            ull wp[8];
            #pragma unroll
            for (int jj = 0; jj < 8; ++jj) wp[jj] = wrow[tx + 8 * jj];
            const float xr[8] = {xa.x, xa.y, xa.z, xa.w, xb.x, xb.y, xb.z, xb.w};
            #pragma unroll
            for (int i = 0; i < 8; ++i) {
                const ull xd = dup2(xr[i]);
                #pragma unroll
                for (int jj = 0; jj < 8; ++jj)
                    accp[i][jj] = ffma2(xd, wp[jj], accp[i][jj]);
            }
        }

        // Packed score: s = rn(rn(c - 2*dot) + wsq); fma(dot,-2,c)==rn(c-2dot).
        const ull* wsqp = reinterpret_cast<const ull*>(wsqs) + ch * (KCHUNK / 2);
        ull wqp[8];
        #pragma unroll
        for (int jj = 0; jj < 8; ++jj) wqp[jj] = wsqp[tx + 8 * jj];
        #pragma unroll
        for (int i = 0; i < 8; ++i) {
            const ull cdup = dup2(cs[ty * 8 + i]);
            #pragma unroll
            for (int jj = 0; jj < 8; ++jj) {   // jj ascending -> k ascending
                float2 s = unpack2(fadd2(ffma2(accp[i][jj], NEG2, cdup), wqp[jj]));
                int k0 = ch * KCHUNK + 2 * (tx + 8 * jj);
                if (s.x < bs[i]) { bs[i] = s.x; bi[i] = k0; }
                if (s.y < bs[i]) { bs[i] = s.y; bi[i] = k0 + 1; }
            }
        }
    }

    // Cross-thread argmin reduction (reuse Ws region): 128 pixels x 8 lanes
    __syncthreads();
    float2* red = reinterpret_cast<float2*>(Ws);
    #pragma unroll
    for (int i = 0; i < 8; ++i)
        red[(ty * 8 + i) * 8 + tx] = make_float2(bs[i], __int_as_float(bi[i]));
    __syncthreads();

    {
        float best = __int_as_float(0x7f800000);
        int   bk   = 0x7fffffff;
        #pragma unroll
        for (int t = 0; t < 8; ++t) {
            float2 e = red[tid * 8 + t];
            float s = e.x; int k = __float_as_int(e.y);
            if (s < best || (s == best && k < bk)) { best = s; bk = k; }
        }
        idxs[tid] = bk;
        out[pbase + tid] = (float)bk;    // discrete_latent (as fp32)
    }
    __syncthreads();

    // Epilogue: quantized (straight-through rounding!) + loss partial
    float* outq = out + QOFF + (size_t)b * (DIM * HW) + hw;
    float lsum = 0.0f;
    #pragma unroll 4
    for (int d = 0; d < DIM; ++d) {
        int k = idxs[tid];
        float q = wt[k * DIM + d];
        float x = Xs[d * RSTR + tid];
        float df = __fsub_rn(q, x);
        lsum = __fmaf_rn(df, df, lsum);
        outq[d * HW + tid] = __fadd_rn(x, df);   // x + (q - x), fp32-rounded like ref
    }
    #pragma unroll
    for (int off = 16; off > 0; off >>= 1)
        lsum += __shfl_down_sync(0xffffffffu, lsum, off);
    if ((tid & 31) == 0) warp_part[tid >> 5] = lsum;
    __syncthreads();
    if (tid == 0) {
        float tot = 0.0f;
        #pragma unroll
        for (int w = 0; w < 4; ++w) tot += warp_part[w];
        g_part[blockIdx.x] = tot;
    }
}

// ---------------------------------------------------------------------------
// finalize: loss = m + 0.25*m,  m = mean((q - x)^2) over all elements
// ---------------------------------------------------------------------------
__global__ void vq_fin(float* __restrict__ out) {
    __shared__ double red[256];
    const int tid = threadIdx.x;
    double t = 0.0;
    #pragma unroll
    for (int r = 0; r < NBLOCKS / 256; ++r)
        t += (double)g_part[tid + r * 256];
    red[tid] = t;
    __syncthreads();
    for (int off = 128; off > 0; off >>= 1) {
        if (tid < off) red[tid] += red[tid + off];
        __syncthreads();
    }
    if (tid == 0) {
        double m = red[0] / NELEM_Q;
        out[LOFF] = (float)(m + 0.25 * m);
    }
}

extern "C" void kernel_launch(void* const* d_in, const int* in_sizes, int n_in,
                              void* d_out, int out_size) {
    (void)in_sizes; (void)n_in; (void)out_size;
    const float* in = (const float*)d_in[0];
    const float* wt = (const float*)d_in[1];
    float* out = (float*)d_out;

    const int smem = 2 * DIM * RSTR * sizeof(float);   // 67584 B
    cudaFuncSetAttribute(vq_main, cudaFuncAttributeMaxDynamicSharedMemorySize, smem);

    vq_main<<<NBLOCKS, THREADS, smem>>>(in, wt, out);
    vq_fin<<<1, 256>>>(out);
}